// round 5
// baseline (speedup 1.0000x reference)
#include <cuda_runtime.h>
#include <math.h>

#define BB 512
#define TT 200
#define HH 128
#define VV 100001
#define G3 384
#define M_TOTAL (BB*TT)   // 102400

// ---------------- scratch ----------------
__device__ float d_embT[(size_t)VV*HH];     // (V, H)  = emb_W^T
__device__ float d_x  [(size_t)M_TOTAL*HH]; // LN1 output
__device__ float d_gi [(size_t)M_TOTAL*G3]; // x @ Wih^T + bih + bhh
__device__ float d_hs [(size_t)M_TOTAL*HH]; // GRU hidden states
__device__ float d_WihT[HH*G3];             // (K=128, N=384)

// ---------------- packed f32x2 helpers ----------------
#define FMA2(acc, a, b) asm("fma.rn.f32x2 %0, %1, %2, %0;" : "+l"(acc) : "l"(a), "l"(b))
__device__ __forceinline__ float f2sum(unsigned long long v) {
    float lo, hi;
    asm("mov.b64 {%0,%1}, %2;" : "=f"(lo), "=f"(hi) : "l"(v));
    return lo + hi;
}
__device__ __forceinline__ unsigned long long f2dup(float a) {
    unsigned long long r;
    asm("mov.b64 %0, {%1,%1};" : "=l"(r) : "f"(a));
    return r;
}
__device__ __forceinline__ void f2unpack(unsigned long long v, float& lo, float& hi) {
    asm("mov.b64 {%0,%1}, %2;" : "=f"(lo), "=f"(hi) : "l"(v));
}

// ---------------- generic 32x32 tiled transpose ----------------
__global__ void transpose_kernel(const float* __restrict__ src, float* __restrict__ dst,
                                 int R, int C) {
    __shared__ float tile[32][33];
    int c0 = blockIdx.x * 32, r0 = blockIdx.y * 32;
    int tx = threadIdx.x, ty = threadIdx.y;  // (32, 8)
    #pragma unroll
    for (int j = 0; j < 32; j += 8) {
        int r = r0 + ty + j, c = c0 + tx;
        if (r < R && c < C) tile[ty + j][tx] = src[(size_t)r * C + c];
    }
    __syncthreads();
    #pragma unroll
    for (int j = 0; j < 32; j += 8) {
        int r = r0 + tx, c = c0 + ty + j;
        if (c < C && r < R) dst[(size_t)c * R + r] = tile[tx][ty + j];
    }
}

// ---------------- block-wide sum over 128 threads ----------------
__device__ __forceinline__ float blocksum128(float v, float* sb) {
    #pragma unroll
    for (int o = 16; o; o >>= 1) v += __shfl_xor_sync(0xffffffffu, v, o);
    if ((threadIdx.x & 31) == 0) sb[threadIdx.x >> 5] = v;
    __syncthreads();
    float r = sb[0] + sb[1] + sb[2] + sb[3];
    __syncthreads();
    return r;
}

// ---------------- K1: embedding gather + LayerNorm1 ----------------
__global__ void embed_ln1(const int* __restrict__ seqs,
                          const float* __restrict__ g1, const float* __restrict__ b1,
                          float* __restrict__ xout) {
    __shared__ float sb[4];
    int idx = blockIdx.x;            // b*TT + t
    int b = idx / TT, t = idx - b * TT;
    int tid = threadIdx.x;           // 128
    int tok = seqs[b * (TT + 1) + t];
    float e  = d_embT[(size_t)tok * HH + tid];
    float mu = blocksum128(e, sb) * (1.0f / HH);
    float d  = e - mu;
    float var = blocksum128(d * d, sb) * (1.0f / HH);
    float xn = d * rsqrtf(var + 1e-8f) * g1[tid] + b1[tid];
    xout[(size_t)idx * HH + tid] = xn;
}

// ---------------- K2: gi = x @ Wih^T + (bih+bhh)  (M=102400, N=384, K=128) ----
// 128m x 128n tiles, 256 threads, 8x8 outputs/thread, packed f32x2 FMA.
#define GPA 132   // As pitch (m-major [m][k])
#define GPB 132   // Bs pitch (k-major [k][n])
__global__ __launch_bounds__(256, 1)
void gemm_gi(const float* __restrict__ x, const float* __restrict__ wT,
             const float* __restrict__ bih, const float* __restrict__ bhh,
             float* __restrict__ gi) {
    extern __shared__ float smem[];
    float* As = smem;             // [m][k] pitch GPA
    float* Bs = smem + 128 * GPA; // [k][n] pitch GPB
    int tid = threadIdx.x;
    int tx = tid & 15, ty = tid >> 4;     // tx: n-group 0..15, ty: m-group 0..15
    int m0 = blockIdx.x * 128;
    int n0 = blockIdx.y * 128;

    // load A tile (float4, direct copy, conflict-free)
    #pragma unroll
    for (int i = tid; i < 128 * 32; i += 256) {
        int m = i >> 5, k4 = i & 31;
        float4 v = *(const float4*)&x[((size_t)(m0 + m)) * 128 + k4 * 4];
        *(float4*)&As[m * GPA + k4 * 4] = v;
    }
    // load B tile (k-major from pre-transposed WihT, float4 direct copy)
    #pragma unroll
    for (int i = tid; i < 128 * 32; i += 256) {
        int k = i >> 5, n4 = i & 31;
        float4 v = *(const float4*)&wT[(size_t)k * G3 + n0 + n4 * 4];
        *(float4*)&Bs[k * GPB + n4 * 4] = v;
    }
    __syncthreads();

    // acc[i][p]: 8 m-rows x 4 packed n-pairs
    unsigned long long acc[8][4];
    #pragma unroll
    for (int i = 0; i < 8; i++)
        #pragma unroll
        for (int p = 0; p < 4; p++) acc[i][p] = 0ull;

    #pragma unroll 4
    for (int k = 0; k < 128; k++) {
        float a_[8];
        #pragma unroll
        for (int i = 0; i < 4; i++) {
            a_[i]     = As[(ty * 4 + i) * GPA + k];
            a_[4 + i] = As[(64 + ty * 4 + i) * GPA + k];
        }
        ulonglong2 b0 = *(const ulonglong2*)&Bs[k * GPB + tx * 4];
        ulonglong2 b1 = *(const ulonglong2*)&Bs[k * GPB + 64 + tx * 4];
        #pragma unroll
        for (int i = 0; i < 8; i++) {
            unsigned long long ap = f2dup(a_[i]);
            FMA2(acc[i][0], ap, b0.x);
            FMA2(acc[i][1], ap, b0.y);
            FMA2(acc[i][2], ap, b1.x);
            FMA2(acc[i][3], ap, b1.y);
        }
    }

    // bias = bih + bhh for this thread's 8 n-columns
    float bv[8];
    #pragma unroll
    for (int j = 0; j < 4; j++) {
        int na = n0 + tx * 4 + j, nb = n0 + 64 + tx * 4 + j;
        bv[j]     = bih[na] + bhh[na];
        bv[4 + j] = bih[nb] + bhh[nb];
    }

    #pragma unroll
    for (int i = 0; i < 8; i++) {
        size_t m = m0 + ((i < 4) ? (ty * 4 + i) : (64 + ty * 4 + (i - 4)));
        float* grow = &gi[m * G3 + n0];
        #pragma unroll
        for (int p = 0; p < 4; p++) {
            float lo, hi;
            f2unpack(acc[i][p], lo, hi);
            int nb = (p < 2) ? (tx * 4 + p * 2) : (64 + tx * 4 + (p - 2) * 2);
            int bb = (p < 2) ? (p * 2) : (4 + (p - 2) * 2);
            float2 st = make_float2(lo + bv[bb], hi + bv[bb + 1]);
            *(float2*)&grow[nb] = st;
        }
    }
}

// ---------------- K3: GRU recurrence ----------------
// 128 CTAs x 4 sequences (1 wave). 512 threads: thread owns 3 Whh rows
// (rp, rp+128, rp+256) x one k-quarter (kp) => 96 floats = 96 regs, NO SPILL.
// Partials combined via shfl_xor over the kp group of 4.
#define HP 144   // hsh per-seq pitch: 4 quarters x 36 floats (conflict-free)
__global__ __launch_bounds__(512, 1)
void gru_rec(const float* __restrict__ gi, const float* __restrict__ Whh,
             float* __restrict__ hs) {
    __shared__ float hsh[4 * HP];     // [seq][quarter*36 + j]
    __shared__ float ghsh[4 * 384];   // [seq][row]
    int tid = threadIdx.x;            // 512
    int kp = tid & 3, rp = tid >> 2;  // kp: k-quarter, rp: 0..127
    int s0 = blockIdx.x * 4;

    // load w into registers: 3 rows x 32 floats (k in [kp*32, kp*32+32))
    unsigned long long w0[16], w1[16], w2[16];
    {
        const float* b0 = Whh + (size_t)rp * 128 + kp * 32;
        const float* b1 = Whh + (size_t)(rp + 128) * 128 + kp * 32;
        const float* b2 = Whh + (size_t)(rp + 256) * 128 + kp * 32;
        #pragma unroll
        for (int i = 0; i < 8; i++) {
            ulonglong2 v0 = ((const ulonglong2*)b0)[i]; w0[2*i] = v0.x; w0[2*i+1] = v0.y;
            ulonglong2 v1 = ((const ulonglong2*)b1)[i]; w1[2*i] = v1.x; w1[2*i+1] = v1.y;
            ulonglong2 v2 = ((const ulonglong2*)b2)[i]; w2[2*i] = v2.x; w2[2*i+1] = v2.y;
        }
    }

    int su = tid >> 7, ju = tid & 127;   // update mapping: 4 seqs x 128 elems
    const float* gp = gi + ((size_t)(s0 + su) * TT) * G3 + ju;
    float* hp = hs + ((size_t)(s0 + su) * TT) * HH + ju;
    float hreg = 0.f;

    for (int i = tid; i < 4 * HP; i += 512) hsh[i] = 0.f;
    __syncthreads();

    for (int t = 0; t < TT; t++) {
        // prefetch gi (consumed after barrier; latency hidden under dot phase)
        float ir  = gp[0];
        float iz  = gp[128];
        float inn = gp[256];

        // dot phase: partial dot over this thread's k-quarter, 3 rows, 4 seqs
        #pragma unroll
        for (int seq = 0; seq < 4; seq++) {
            unsigned long long a0 = 0ull, a1 = 0ull, a2 = 0ull;
            const ulonglong2* hq = (const ulonglong2*)&hsh[seq * HP + kp * 36];
            #pragma unroll
            for (int i = 0; i < 8; i++) {
                ulonglong2 hv = hq[i];
                FMA2(a0, w0[2*i], hv.x); FMA2(a0, w0[2*i+1], hv.y);
                FMA2(a1, w1[2*i], hv.x); FMA2(a1, w1[2*i+1], hv.y);
                FMA2(a2, w2[2*i], hv.x); FMA2(a2, w2[2*i+1], hv.y);
            }
            float s0v = f2sum(a0), s1v = f2sum(a1), s2v = f2sum(a2);
            s0v += __shfl_xor_sync(0xffffffffu, s0v, 1);
            s0v += __shfl_xor_sync(0xffffffffu, s0v, 2);
            s1v += __shfl_xor_sync(0xffffffffu, s1v, 1);
            s1v += __shfl_xor_sync(0xffffffffu, s1v, 2);
            s2v += __shfl_xor_sync(0xffffffffu, s2v, 1);
            s2v += __shfl_xor_sync(0xffffffffu, s2v, 2);
            if (kp == 0) {
                ghsh[seq * 384 + rp]       = s0v;
                ghsh[seq * 384 + 128 + rp] = s1v;
                ghsh[seq * 384 + 256 + rp] = s2v;
            }
        }
        __syncthreads();

        // update phase (bhh already folded into gi)
        {
            const float* gh = &ghsh[su * 384];
            float hr = gh[ju];
            float hz = gh[128 + ju];
            float hn = gh[256 + ju];
            float r = 1.f / (1.f + __expf(-(ir + hr)));
            float z = 1.f / (1.f + __expf(-(iz + hz)));
            float n = tanhf(inn + r * hn);
            float hnew = (1.f - z) * n + z * hreg;
            hreg = hnew;
            hsh[su * HP + (ju >> 5) * 36 + (ju & 31)] = hnew;
            *hp = hnew;
            gp += G3;
            hp += HH;
        }
        __syncthreads();
    }
}

// ---------------- K4: LayerNorm2 + pos/neg dot products ----------------
__global__ void final_logits(const int* __restrict__ seqs, const int* __restrict__ negs,
                             const float* __restrict__ g2, const float* __restrict__ b2,
                             float* __restrict__ out) {
    __shared__ float sb[4];
    int idx = blockIdx.x;
    int b = idx / TT, t = idx - b * TT;
    int tid = threadIdx.x;          // 128
    float v  = d_hs[(size_t)idx * HH + tid];
    float mu = blocksum128(v, sb) * (1.0f / HH);
    float d  = v - mu;
    float var = blocksum128(d * d, sb) * (1.0f / HH);
    float ln = d * rsqrtf(var + 1e-8f) * g2[tid] + b2[tid];

    int pt = seqs[b * (TT + 1) + t + 1];
    int nt = negs[b * (TT + 1) + t + 1];
    float pv = ln * d_embT[(size_t)pt * HH + tid];
    float nv = ln * d_embT[(size_t)nt * HH + tid];
    float ps = blocksum128(pv, sb);
    float ns = blocksum128(nv, sb);
    if (tid == 0) {
        out[idx]           = ps;
        out[M_TOTAL + idx] = ns;
    }
}

// ---------------- launch ----------------
extern "C" void kernel_launch(void* const* d_in, const int* in_sizes, int n_in,
                              void* d_out, int out_size) {
    const int*   input_seqs = (const int*)  d_in[0];
    const int*   negs       = (const int*)  d_in[1];
    const float* emb_W      = (const float*)d_in[2];
    const float* Wih        = (const float*)d_in[3];
    const float* Whh        = (const float*)d_in[4];
    const float* bih        = (const float*)d_in[5];
    const float* bhh        = (const float*)d_in[6];
    const float* ln1_g      = (const float*)d_in[7];
    const float* ln1_b      = (const float*)d_in[8];
    const float* ln2_g      = (const float*)d_in[9];
    const float* ln2_b      = (const float*)d_in[10];
    float* out = (float*)d_out;

    float* p_embT; cudaGetSymbolAddress((void**)&p_embT, d_embT);
    float* p_x;    cudaGetSymbolAddress((void**)&p_x,    d_x);
    float* p_gi;   cudaGetSymbolAddress((void**)&p_gi,   d_gi);
    float* p_hs;   cudaGetSymbolAddress((void**)&p_hs,   d_hs);
    float* p_WihT; cudaGetSymbolAddress((void**)&p_WihT, d_WihT);

    transpose_kernel<<<dim3((VV + 31) / 32, 4), dim3(32, 8)>>>(emb_W, p_embT, HH, VV);
    transpose_kernel<<<dim3(4, 12), dim3(32, 8)>>>(Wih, p_WihT, G3, HH);

    embed_ln1<<<M_TOTAL, 128>>>(input_seqs, ln1_g, ln1_b, p_x);

    const int gemm_smem = 2 * 128 * GPA * sizeof(float);   // 135168 B
    cudaFuncSetAttribute(gemm_gi, cudaFuncAttributeMaxDynamicSharedMemorySize, gemm_smem);
    gemm_gi<<<dim3(M_TOTAL / 128, G3 / 128), 256, gemm_smem>>>(p_x, p_WihT, bih, bhh, p_gi);

    gru_rec<<<BB / 4, 512>>>(p_gi, Whh, p_hs);

    final_logits<<<M_TOTAL, 128>>>(input_seqs, negs, ln2_g, ln2_b, out);
}

// round 6
// speedup vs baseline: 1.6268x; 1.6268x over previous
#include <cuda_runtime.h>
#include <math.h>

#define BB 512
#define TT 200
#define HH 128
#define VV 100001
#define G3 384
#define M_TOTAL (BB*TT)   // 102400

// ---------------- scratch ----------------
__device__ float d_embT[(size_t)VV*HH];     // (V, H)  = emb_W^T
__device__ float d_x  [(size_t)M_TOTAL*HH]; // LN1 output
__device__ float d_gi [(size_t)M_TOTAL*G3]; // x @ Wih^T + bih + bhh
__device__ float d_hs [(size_t)M_TOTAL*HH]; // GRU hidden states
__device__ float d_WihT[HH*G3];             // (K=128, N=384)

// ---------------- packed f32x2 helpers ----------------
#define FMA2(acc, a, b) asm("fma.rn.f32x2 %0, %1, %2, %0;" : "+l"(acc) : "l"(a), "l"(b))
__device__ __forceinline__ float f2sum(unsigned long long v) {
    float lo, hi;
    asm("mov.b64 {%0,%1}, %2;" : "=f"(lo), "=f"(hi) : "l"(v));
    return lo + hi;
}
__device__ __forceinline__ unsigned long long f2dup(float a) {
    unsigned long long r;
    asm("mov.b64 %0, {%1,%1};" : "=l"(r) : "f"(a));
    return r;
}
__device__ __forceinline__ void f2unpack(unsigned long long v, float& lo, float& hi) {
    asm("mov.b64 {%0,%1}, %2;" : "=f"(lo), "=f"(hi) : "l"(v));
}

// ---------------- generic 32x32 tiled transpose ----------------
__global__ void transpose_kernel(const float* __restrict__ src, float* __restrict__ dst,
                                 int R, int C) {
    __shared__ float tile[32][33];
    int c0 = blockIdx.x * 32, r0 = blockIdx.y * 32;
    int tx = threadIdx.x, ty = threadIdx.y;  // (32, 8)
    #pragma unroll
    for (int j = 0; j < 32; j += 8) {
        int r = r0 + ty + j, c = c0 + tx;
        if (r < R && c < C) tile[ty + j][tx] = src[(size_t)r * C + c];
    }
    __syncthreads();
    #pragma unroll
    for (int j = 0; j < 32; j += 8) {
        int r = r0 + tx, c = c0 + ty + j;
        if (c < C && r < R) dst[(size_t)c * R + r] = tile[tx][ty + j];
    }
}

// ---------------- block-wide sum over 128 threads ----------------
__device__ __forceinline__ float blocksum128(float v, float* sb) {
    #pragma unroll
    for (int o = 16; o; o >>= 1) v += __shfl_xor_sync(0xffffffffu, v, o);
    if ((threadIdx.x & 31) == 0) sb[threadIdx.x >> 5] = v;
    __syncthreads();
    float r = sb[0] + sb[1] + sb[2] + sb[3];
    __syncthreads();
    return r;
}

// ---------------- K1: embedding gather + LayerNorm1 ----------------
__global__ void embed_ln1(const int* __restrict__ seqs,
                          const float* __restrict__ g1, const float* __restrict__ b1,
                          float* __restrict__ xout) {
    __shared__ float sb[4];
    int idx = blockIdx.x;            // b*TT + t
    int b = idx / TT, t = idx - b * TT;
    int tid = threadIdx.x;           // 128
    int tok = seqs[b * (TT + 1) + t];
    float e  = d_embT[(size_t)tok * HH + tid];
    float mu = blocksum128(e, sb) * (1.0f / HH);
    float d  = e - mu;
    float var = blocksum128(d * d, sb) * (1.0f / HH);
    float xn = d * rsqrtf(var + 1e-8f) * g1[tid] + b1[tid];
    xout[(size_t)idx * HH + tid] = xn;
}

// ---------------- K2: gi = x @ Wih^T + (bih+bhh)  (M=102400, N=384, K=128) ----
// R3 proven config: 128m x 64n tiles, 256 threads, 2 CTAs/SM, packed f32x2 FMA.
#define GPA 132   // As pitch (floats)
#define GPB 68    // Bs pitch (floats)
__global__ __launch_bounds__(256, 2)
void gemm_gi(const float* __restrict__ x, const float* __restrict__ wT,
             const float* __restrict__ bih, const float* __restrict__ bhh,
             float* __restrict__ gi) {
    extern __shared__ float smem[];
    float* As = smem;            // [m 0..127][k pitch GPA]
    float* Bs = smem + 128 * GPA;// [k 0..127][n pitch GPB]
    int tid = threadIdx.x;
    int tx = tid & 7, ty = tid >> 3;       // tx: n-group (0..7), ty: m-group (0..31)
    int m0 = blockIdx.x * 128;
    int n0 = blockIdx.y * 64;

    // load A tile (float4, direct copy)
    #pragma unroll
    for (int i = tid; i < 128 * 32; i += 256) {
        int m = i >> 5, k4 = i & 31;
        float4 v = *(const float4*)&x[((size_t)(m0 + m)) * 128 + k4 * 4];
        *(float4*)&As[m * GPA + k4 * 4] = v;
    }
    // load B tile (k-major from pre-transposed WihT)
    #pragma unroll
    for (int i = tid; i < 128 * 16; i += 256) {
        int k = i >> 4, n4 = i & 15;
        float4 v = *(const float4*)&wT[(size_t)k * G3 + n0 + n4 * 4];
        *(float4*)&Bs[k * GPB + n4 * 4] = v;
    }
    __syncthreads();

    // acc[i][p]: 4 m-rows x 4 packed n-pairs
    unsigned long long acc[4][4];
    #pragma unroll
    for (int i = 0; i < 4; i++)
        #pragma unroll
        for (int p = 0; p < 4; p++) acc[i][p] = 0ull;

    #pragma unroll 8
    for (int kc = 0; kc < 32; kc++) {
        float4 a4[4];
        #pragma unroll
        for (int i = 0; i < 4; i++)
            a4[i] = *(const float4*)&As[(ty * 4 + i) * GPA + kc * 4];
        #pragma unroll
        for (int kk = 0; kk < 4; kk++) {
            int krow = kc * 4 + kk;
            ulonglong2 bl = *(const ulonglong2*)&Bs[krow * GPB + tx * 4];
            ulonglong2 bh = *(const ulonglong2*)&Bs[krow * GPB + 32 + tx * 4];
            #pragma unroll
            for (int i = 0; i < 4; i++) {
                float av = (kk == 0) ? a4[i].x : (kk == 1) ? a4[i].y
                         : (kk == 2) ? a4[i].z : a4[i].w;
                unsigned long long ap = f2dup(av);
                FMA2(acc[i][0], ap, bl.x);
                FMA2(acc[i][1], ap, bl.y);
                FMA2(acc[i][2], ap, bh.x);
                FMA2(acc[i][3], ap, bh.y);
            }
        }
    }

    // bias = bih + bhh for this thread's 8 n-columns
    float bv[8];
    #pragma unroll
    for (int j = 0; j < 4; j++) {
        int na = n0 + tx * 4 + j, nb = n0 + 32 + tx * 4 + j;
        bv[j]     = bih[na] + bhh[na];
        bv[4 + j] = bih[nb] + bhh[nb];
    }

    #pragma unroll
    for (int i = 0; i < 4; i++) {
        size_t m = m0 + ty * 4 + i;
        float* grow = &gi[m * G3 + n0];
        #pragma unroll
        for (int p = 0; p < 4; p++) {
            float lo, hi;
            f2unpack(acc[i][p], lo, hi);
            int nb = (p < 2) ? (tx * 4 + p * 2) : (32 + tx * 4 + (p - 2) * 2);
            int bb = (p < 2) ? (p * 2) : (4 + (p - 2) * 2);
            float2 st = make_float2(lo + bv[bb], hi + bv[bb + 1]);
            *(float2*)&grow[nb] = st;
        }
    }
}

// ---------------- K3: GRU recurrence ----------------
// 128 CTAs x 4 sequences (1 wave), 512 threads. Thread owns 3 Whh rows
// (rp, rp+128, rp+256) x one k-quarter (kp): 96 w-floats = 96 regs.
// Seq loop NOT unrolled (one seq's temps live at a time) to stay under the
// 128-reg cap. Inner k loop fully unrolled (register-array constant indexing).
#define HP 144   // hsh per-seq pitch: 4 quarters x 36 floats (conflict-free)
__global__ __launch_bounds__(512)
void gru_rec(const float* __restrict__ gi, const float* __restrict__ Whh,
             float* __restrict__ hs) {
    __shared__ float hsh[4 * HP];     // [seq][quarter*36 + j]
    __shared__ float ghsh[4 * 384];   // [seq][row]
    int tid = threadIdx.x;            // 512
    int kp = tid & 3, rp = tid >> 2;  // kp: k-quarter, rp: 0..127
    int s0 = blockIdx.x * 4;

    // w[0..15]: row rp, w[16..31]: row rp+128, w[32..47]: row rp+256
    unsigned long long w[48];
    {
        const float* wb = Whh + (size_t)rp * 128 + kp * 32;
        #pragma unroll
        for (int r = 0; r < 3; r++) {
            const ulonglong2* p = (const ulonglong2*)(wb + (size_t)r * 128 * 128);
            #pragma unroll
            for (int i = 0; i < 8; i++) {
                ulonglong2 v = p[i];
                w[r * 16 + 2 * i]     = v.x;
                w[r * 16 + 2 * i + 1] = v.y;
            }
        }
    }

    // update mapping: all 512 threads active (4 seqs x 128 elems)
    int su = tid >> 7, ju = tid & 127;
    const float* gp = gi + ((size_t)(s0 + su) * TT) * G3 + ju;
    float* hp = hs + ((size_t)(s0 + su) * TT) * HH + ju;
    float hreg = 0.f;

    for (int i = tid; i < 4 * HP; i += 512) hsh[i] = 0.f;
    __syncthreads();

    for (int t = 0; t < TT; t++) {
        // prefetch gi (L2 latency hides under dot phase)
        float ir  = gp[0];
        float iz  = gp[128];
        float inn = gp[256];

        // dot phase: one seq at a time (limits live registers)
        #pragma unroll 1
        for (int seq = 0; seq < 4; seq++) {
            unsigned long long a0 = 0ull, a1 = 0ull, a2 = 0ull;
            const ulonglong2* hq = (const ulonglong2*)&hsh[seq * HP + kp * 36];
            #pragma unroll
            for (int i = 0; i < 8; i++) {
                ulonglong2 hv = hq[i];
                FMA2(a0, w[2 * i],      hv.x); FMA2(a0, w[2 * i + 1],      hv.y);
                FMA2(a1, w[16 + 2 * i], hv.x); FMA2(a1, w[16 + 2 * i + 1], hv.y);
                FMA2(a2, w[32 + 2 * i], hv.x); FMA2(a2, w[32 + 2 * i + 1], hv.y);
            }
            float v0 = f2sum(a0), v1 = f2sum(a1), v2 = f2sum(a2);
            v0 += __shfl_xor_sync(0xffffffffu, v0, 1);
            v0 += __shfl_xor_sync(0xffffffffu, v0, 2);
            v1 += __shfl_xor_sync(0xffffffffu, v1, 1);
            v1 += __shfl_xor_sync(0xffffffffu, v1, 2);
            v2 += __shfl_xor_sync(0xffffffffu, v2, 1);
            v2 += __shfl_xor_sync(0xffffffffu, v2, 2);
            if (kp == 0) {
                ghsh[seq * 384 + rp]       = v0;
                ghsh[seq * 384 + 128 + rp] = v1;
                ghsh[seq * 384 + 256 + rp] = v2;
            }
        }
        __syncthreads();

        // update phase (bhh already folded into gi)
        {
            const float* gh = &ghsh[su * 384];
            float hr = gh[ju];
            float hz = gh[128 + ju];
            float hn = gh[256 + ju];
            float r = 1.f / (1.f + __expf(-(ir + hr)));
            float z = 1.f / (1.f + __expf(-(iz + hz)));
            float n = tanhf(inn + r * hn);
            float hnew = (1.f - z) * n + z * hreg;
            hreg = hnew;
            hsh[su * HP + (ju >> 5) * 36 + (ju & 31)] = hnew;
            *hp = hnew;
            gp += G3;
            hp += HH;
        }
        __syncthreads();
    }
}

// ---------------- K4: LayerNorm2 + pos/neg dot products ----------------
__global__ void final_logits(const int* __restrict__ seqs, const int* __restrict__ negs,
                             const float* __restrict__ g2, const float* __restrict__ b2,
                             float* __restrict__ out) {
    __shared__ float sb[4];
    int idx = blockIdx.x;
    int b = idx / TT, t = idx - b * TT;
    int tid = threadIdx.x;          // 128
    float v  = d_hs[(size_t)idx * HH + tid];
    float mu = blocksum128(v, sb) * (1.0f / HH);
    float d  = v - mu;
    float var = blocksum128(d * d, sb) * (1.0f / HH);
    float ln = d * rsqrtf(var + 1e-8f) * g2[tid] + b2[tid];

    int pt = seqs[b * (TT + 1) + t + 1];
    int nt = negs[b * (TT + 1) + t + 1];
    float pv = ln * d_embT[(size_t)pt * HH + tid];
    float nv = ln * d_embT[(size_t)nt * HH + tid];
    float ps = blocksum128(pv, sb);
    float ns = blocksum128(nv, sb);
    if (tid == 0) {
        out[idx]           = ps;
        out[M_TOTAL + idx] = ns;
    }
}

// ---------------- launch ----------------
extern "C" void kernel_launch(void* const* d_in, const int* in_sizes, int n_in,
                              void* d_out, int out_size) {
    const int*   input_seqs = (const int*)  d_in[0];
    const int*   negs       = (const int*)  d_in[1];
    const float* emb_W      = (const float*)d_in[2];
    const float* Wih        = (const float*)d_in[3];
    const float* Whh        = (const float*)d_in[4];
    const float* bih        = (const float*)d_in[5];
    const float* bhh        = (const float*)d_in[6];
    const float* ln1_g      = (const float*)d_in[7];
    const float* ln1_b      = (const float*)d_in[8];
    const float* ln2_g      = (const float*)d_in[9];
    const float* ln2_b      = (const float*)d_in[10];
    float* out = (float*)d_out;

    float* p_embT; cudaGetSymbolAddress((void**)&p_embT, d_embT);
    float* p_x;    cudaGetSymbolAddress((void**)&p_x,    d_x);
    float* p_gi;   cudaGetSymbolAddress((void**)&p_gi,   d_gi);
    float* p_hs;   cudaGetSymbolAddress((void**)&p_hs,   d_hs);
    float* p_WihT; cudaGetSymbolAddress((void**)&p_WihT, d_WihT);

    transpose_kernel<<<dim3((VV + 31) / 32, 4), dim3(32, 8)>>>(emb_W, p_embT, HH, VV);
    transpose_kernel<<<dim3(4, 12), dim3(32, 8)>>>(Wih, p_WihT, G3, HH);

    embed_ln1<<<M_TOTAL, 128>>>(input_seqs, ln1_g, ln1_b, p_x);

    const int gemm_smem = (128 * GPA + 128 * GPB) * sizeof(float);   // 102400 B
    cudaFuncSetAttribute(gemm_gi, cudaFuncAttributeMaxDynamicSharedMemorySize, gemm_smem);
    gemm_gi<<<dim3(M_TOTAL / 128, G3 / 64), 256, gemm_smem>>>(p_x, p_WihT, bih, bhh, p_gi);

    gru_rec<<<BB / 4, 512>>>(p_gi, Whh, p_hs);

    final_logits<<<M_TOTAL, 128>>>(input_seqs, negs, ln2_g, ln2_b, out);
}

// round 7
// speedup vs baseline: 1.6835x; 1.0348x over previous
#include <cuda_runtime.h>
#include <math.h>

#define BB 512
#define TT 200
#define HH 128
#define VV 100001
#define G3 384
#define M_TOTAL (BB*TT)   // 102400

// ---------------- scratch ----------------
__device__ float d_embT[(size_t)VV*HH];     // (V, H)  = emb_W^T
__device__ float d_x  [(size_t)M_TOTAL*HH]; // LN1 output
__device__ float d_gi [(size_t)M_TOTAL*G3]; // x @ Wih^T + bih + bhh
__device__ float d_hs [(size_t)M_TOTAL*HH]; // GRU hidden states
__device__ float d_WihT[HH*G3];             // (K=128, N=384)

// ---------------- packed f32x2 helpers ----------------
#define FMA2(acc, a, b) asm("fma.rn.f32x2 %0, %1, %2, %0;" : "+l"(acc) : "l"(a), "l"(b))
__device__ __forceinline__ float f2sum(unsigned long long v) {
    float lo, hi;
    asm("mov.b64 {%0,%1}, %2;" : "=f"(lo), "=f"(hi) : "l"(v));
    return lo + hi;
}
__device__ __forceinline__ unsigned long long f2dup(float a) {
    unsigned long long r;
    asm("mov.b64 %0, {%1,%1};" : "=l"(r) : "f"(a));
    return r;
}
__device__ __forceinline__ void f2unpack(unsigned long long v, float& lo, float& hi) {
    asm("mov.b64 {%0,%1}, %2;" : "=f"(lo), "=f"(hi) : "l"(v));
}

// fast sigmoid / tanh via MUFU (ex2 + rcp approx): err ~1e-7
__device__ __forceinline__ float sigf(float x) {
    float e, r;
    asm("ex2.approx.f32 %0, %1;" : "=f"(e) : "f"(-1.4426950408889634f * x));
    asm("rcp.approx.f32 %0, %1;" : "=f"(r) : "f"(1.0f + e));
    return r;
}
__device__ __forceinline__ float tanhfast(float x) {
    return fmaf(2.0f, sigf(2.0f * x), -1.0f);
}

// ---------------- generic 32x32 tiled transpose ----------------
__global__ void transpose_kernel(const float* __restrict__ src, float* __restrict__ dst,
                                 int R, int C) {
    __shared__ float tile[32][33];
    int c0 = blockIdx.x * 32, r0 = blockIdx.y * 32;
    int tx = threadIdx.x, ty = threadIdx.y;  // (32, 8)
    #pragma unroll
    for (int j = 0; j < 32; j += 8) {
        int r = r0 + ty + j, c = c0 + tx;
        if (r < R && c < C) tile[ty + j][tx] = src[(size_t)r * C + c];
    }
    __syncthreads();
    #pragma unroll
    for (int j = 0; j < 32; j += 8) {
        int r = r0 + tx, c = c0 + ty + j;
        if (c < C && r < R) dst[(size_t)c * R + r] = tile[tx][ty + j];
    }
}

// ---------------- block-wide sum over 128 threads ----------------
__device__ __forceinline__ float blocksum128(float v, float* sb) {
    #pragma unroll
    for (int o = 16; o; o >>= 1) v += __shfl_xor_sync(0xffffffffu, v, o);
    if ((threadIdx.x & 31) == 0) sb[threadIdx.x >> 5] = v;
    __syncthreads();
    float r = sb[0] + sb[1] + sb[2] + sb[3];
    __syncthreads();
    return r;
}

// ---------------- K1: embedding gather + LayerNorm1 ----------------
__global__ void embed_ln1(const int* __restrict__ seqs,
                          const float* __restrict__ g1, const float* __restrict__ b1,
                          float* __restrict__ xout) {
    __shared__ float sb[4];
    int idx = blockIdx.x;            // b*TT + t
    int b = idx / TT, t = idx - b * TT;
    int tid = threadIdx.x;           // 128
    int tok = seqs[b * (TT + 1) + t];
    float e  = d_embT[(size_t)tok * HH + tid];
    float mu = blocksum128(e, sb) * (1.0f / HH);
    float d  = e - mu;
    float var = blocksum128(d * d, sb) * (1.0f / HH);
    float xn = d * rsqrtf(var + 1e-8f) * g1[tid] + b1[tid];
    xout[(size_t)idx * HH + tid] = xn;
}

// ---------------- K2: gi = x @ Wih^T + (bih+bhh)  (M=102400, N=384, K=128) ----
// 64m x 64n tiles, 256 threads, 3 CTAs/SM (69KB smem), 4m x 4n per thread.
#define GPA 132   // As pitch (floats), [m][k]
#define GPB 68    // Bs pitch (floats), [k][n]
__global__ __launch_bounds__(256, 3)
void gemm_gi(const float* __restrict__ x, const float* __restrict__ wT,
             const float* __restrict__ bih, const float* __restrict__ bhh,
             float* __restrict__ gi) {
    extern __shared__ float smem[];
    float* As = smem;            // [m 0..63][k 0..127]
    float* Bs = smem + 64 * GPA; // [k 0..127][n 0..63]
    int tid = threadIdx.x;
    int tx = tid & 15, ty = tid >> 4;   // tx: n-group 0..15, ty: m-group 0..15
    int m0 = blockIdx.x * 64;
    int n0 = blockIdx.y * 64;

    // stage A tile: 64 rows x 32 float4
    #pragma unroll
    for (int i = tid; i < 64 * 32; i += 256) {
        int m = i >> 5, k4 = i & 31;
        float4 v = *(const float4*)&x[((size_t)(m0 + m)) * 128 + k4 * 4];
        *(float4*)&As[m * GPA + k4 * 4] = v;
    }
    // stage B tile: 128 k x 16 float4
    #pragma unroll
    for (int i = tid; i < 128 * 16; i += 256) {
        int k = i >> 4, n4 = i & 15;
        float4 v = *(const float4*)&wT[(size_t)k * G3 + n0 + n4 * 4];
        *(float4*)&Bs[k * GPB + n4 * 4] = v;
    }
    __syncthreads();

    unsigned long long acc[4][2];   // 4 m-rows x 2 packed n-pairs (4n)
    #pragma unroll
    for (int i = 0; i < 4; i++) { acc[i][0] = 0ull; acc[i][1] = 0ull; }

    #pragma unroll 8
    for (int kc = 0; kc < 32; kc++) {
        float4 a4[4];
        #pragma unroll
        for (int i = 0; i < 4; i++)
            a4[i] = *(const float4*)&As[(ty * 4 + i) * GPA + kc * 4];
        #pragma unroll
        for (int kk = 0; kk < 4; kk++) {
            ulonglong2 b = *(const ulonglong2*)&Bs[(kc * 4 + kk) * GPB + tx * 4];
            #pragma unroll
            for (int i = 0; i < 4; i++) {
                float av = (kk == 0) ? a4[i].x : (kk == 1) ? a4[i].y
                         : (kk == 2) ? a4[i].z : a4[i].w;
                unsigned long long ap = f2dup(av);
                FMA2(acc[i][0], ap, b.x);
                FMA2(acc[i][1], ap, b.y);
            }
        }
    }

    // bias = bih + bhh for this thread's 4 n-columns
    float bv[4];
    #pragma unroll
    for (int j = 0; j < 4; j++) {
        int n = n0 + tx * 4 + j;
        bv[j] = bih[n] + bhh[n];
    }

    #pragma unroll
    for (int i = 0; i < 4; i++) {
        size_t m = m0 + ty * 4 + i;
        float l0, h0, l1, h1;
        f2unpack(acc[i][0], l0, h0);
        f2unpack(acc[i][1], l1, h1);
        float4 st = make_float4(l0 + bv[0], h0 + bv[1], l1 + bv[2], h1 + bv[3]);
        *(float4*)&gi[m * G3 + n0 + tx * 4] = st;
    }
}

// ---------------- K3: GRU recurrence ----------------
// 128 CTAs x 4 sequences, 512 threads. Thread owns 3 Whh rows x one k-quarter
// (96 w-regs). Cross-kp reduction via SMEM PARTIALS (no shfl): each kp lane
// writes its f2sum partial; update threads sum the 4 partials.
#define HP   144    // hsh per-seq pitch: 4 quarters x 36 floats
#define GHPS 1544   // ghp per-kp stride (== 8 mod 32 -> conflict-free STS)
__global__ __launch_bounds__(512)
void gru_rec(const float* __restrict__ gi, const float* __restrict__ Whh,
             float* __restrict__ hs) {
    __shared__ float hsh[4 * HP];      // [seq][quarter*36 + j]
    __shared__ float ghp[4 * GHPS];    // [kp][seq*384 + gate*128 + rp]
    int tid = threadIdx.x;             // 512
    int kp = tid & 3, rp = tid >> 2;   // kp: k-quarter, rp: 0..127
    int s0 = blockIdx.x * 4;

    // w[0..15]: row rp, w[16..31]: row rp+128, w[32..47]: row rp+256
    unsigned long long w[48];
    {
        const float* wb = Whh + (size_t)rp * 128 + kp * 32;
        #pragma unroll
        for (int r = 0; r < 3; r++) {
            const ulonglong2* p = (const ulonglong2*)(wb + (size_t)r * 128 * 128);
            #pragma unroll
            for (int i = 0; i < 8; i++) {
                ulonglong2 v = p[i];
                w[r * 16 + 2 * i]     = v.x;
                w[r * 16 + 2 * i + 1] = v.y;
            }
        }
    }

    // update mapping: all 512 threads (4 seqs x 128 elems)
    int su = tid >> 7, ju = tid & 127;
    const float* gp = gi + ((size_t)(s0 + su) * TT) * G3 + ju;
    float* hp = hs + ((size_t)(s0 + su) * TT) * HH + ju;
    float hreg = 0.f;

    for (int i = tid; i < 4 * HP; i += 512) hsh[i] = 0.f;
    __syncthreads();

    float* gout = &ghp[kp * GHPS + rp];

    for (int t = 0; t < TT; t++) {
        // prefetch gi (L2 latency hides under dot phase)
        float ir  = gp[0];
        float iz  = gp[128];
        float inn = gp[256];

        // dot phase: one seq at a time; write kp-partials to smem (no shfl)
        #pragma unroll 1
        for (int seq = 0; seq < 4; seq++) {
            unsigned long long a0 = 0ull, a1 = 0ull, a2 = 0ull;
            const ulonglong2* hq = (const ulonglong2*)&hsh[seq * HP + kp * 36];
            #pragma unroll
            for (int i = 0; i < 8; i++) {
                ulonglong2 hv = hq[i];
                FMA2(a0, w[2 * i],      hv.x); FMA2(a0, w[2 * i + 1],      hv.y);
                FMA2(a1, w[16 + 2 * i], hv.x); FMA2(a1, w[16 + 2 * i + 1], hv.y);
                FMA2(a2, w[32 + 2 * i], hv.x); FMA2(a2, w[32 + 2 * i + 1], hv.y);
            }
            float* go = gout + seq * 384;
            go[0]   = f2sum(a0);
            go[128] = f2sum(a1);
            go[256] = f2sum(a2);
        }
        __syncthreads();

        // update phase: sum 4 kp-partials per gate, then gate math
        {
            int u = su * 384 + ju;
            const float* g0 = &ghp[u];
            const float* g1 = &ghp[GHPS + u];
            const float* g2 = &ghp[2 * GHPS + u];
            const float* g3 = &ghp[3 * GHPS + u];
            float hr = (g0[0]   + g1[0])   + (g2[0]   + g3[0]);
            float hz = (g0[128] + g1[128]) + (g2[128] + g3[128]);
            float hn = (g0[256] + g1[256]) + (g2[256] + g3[256]);
            float r = sigf(ir + hr);
            float z = sigf(iz + hz);
            float n = tanhfast(inn + r * hn);
            float hnew = (1.f - z) * n + z * hreg;
            hreg = hnew;
            hsh[su * HP + (ju >> 5) * 36 + (ju & 31)] = hnew;
            *hp = hnew;
            gp += G3;
            hp += HH;
        }
        __syncthreads();
    }
}

// ---------------- K4: LayerNorm2 + pos/neg dot products ----------------
__global__ void final_logits(const int* __restrict__ seqs, const int* __restrict__ negs,
                             const float* __restrict__ g2, const float* __restrict__ b2,
                             float* __restrict__ out) {
    __shared__ float sb[4];
    int idx = blockIdx.x;
    int b = idx / TT, t = idx - b * TT;
    int tid = threadIdx.x;          // 128
    float v  = d_hs[(size_t)idx * HH + tid];
    float mu = blocksum128(v, sb) * (1.0f / HH);
    float d  = v - mu;
    float var = blocksum128(d * d, sb) * (1.0f / HH);
    float ln = d * rsqrtf(var + 1e-8f) * g2[tid] + b2[tid];

    int pt = seqs[b * (TT + 1) + t + 1];
    int nt = negs[b * (TT + 1) + t + 1];
    float pv = ln * d_embT[(size_t)pt * HH + tid];
    float nv = ln * d_embT[(size_t)nt * HH + tid];
    float ps = blocksum128(pv, sb);
    float ns = blocksum128(nv, sb);
    if (tid == 0) {
        out[idx]           = ps;
        out[M_TOTAL + idx] = ns;
    }
}

// ---------------- launch ----------------
extern "C" void kernel_launch(void* const* d_in, const int* in_sizes, int n_in,
                              void* d_out, int out_size) {
    const int*   input_seqs = (const int*)  d_in[0];
    const int*   negs       = (const int*)  d_in[1];
    const float* emb_W      = (const float*)d_in[2];
    const float* Wih        = (const float*)d_in[3];
    const float* Whh        = (const float*)d_in[4];
    const float* bih        = (const float*)d_in[5];
    const float* bhh        = (const float*)d_in[6];
    const float* ln1_g      = (const float*)d_in[7];
    const float* ln1_b      = (const float*)d_in[8];
    const float* ln2_g      = (const float*)d_in[9];
    const float* ln2_b      = (const float*)d_in[10];
    float* out = (float*)d_out;

    float* p_embT; cudaGetSymbolAddress((void**)&p_embT, d_embT);
    float* p_x;    cudaGetSymbolAddress((void**)&p_x,    d_x);
    float* p_gi;   cudaGetSymbolAddress((void**)&p_gi,   d_gi);
    float* p_hs;   cudaGetSymbolAddress((void**)&p_hs,   d_hs);
    float* p_WihT; cudaGetSymbolAddress((void**)&p_WihT, d_WihT);

    transpose_kernel<<<dim3((VV + 31) / 32, 4), dim3(32, 8)>>>(emb_W, p_embT, HH, VV);
    transpose_kernel<<<dim3(4, 12), dim3(32, 8)>>>(Wih, p_WihT, G3, HH);

    embed_ln1<<<M_TOTAL, 128>>>(input_seqs, ln1_g, ln1_b, p_x);

    const int gemm_smem = (64 * GPA + 128 * GPB) * sizeof(float);   // 68608 B
    cudaFuncSetAttribute(gemm_gi, cudaFuncAttributeMaxDynamicSharedMemorySize, gemm_smem);
    gemm_gi<<<dim3(M_TOTAL / 64, G3 / 64), 256, gemm_smem>>>(p_x, p_WihT, bih, bhh, p_gi);

    gru_rec<<<BB / 4, 512>>>(p_gi, Whh, p_hs);

    final_logits<<<M_TOTAL, 128>>>(input_seqs, negs, ln2_g, ln2_b, out);
}

// round 9
// speedup vs baseline: 2.0481x; 1.2166x over previous
#include <cuda_runtime.h>
#include <cuda_bf16.h>
#include <math.h>
#include <cstdint>

#define BB 512
#define TT 200
#define HH 128
#define VV 100001
#define G3 384
#define M_TOTAL (BB*TT)   // 102400

// ---------------- scratch ----------------
__device__ float d_embT[(size_t)VV*HH];            // (V, H) = emb_W^T
__device__ __nv_bfloat16 d_xhi[(size_t)M_TOTAL*HH];
__device__ __nv_bfloat16 d_xlo[(size_t)M_TOTAL*HH];
__device__ __nv_bfloat16 d_whi[G3*HH];
__device__ __nv_bfloat16 d_wlo[G3*HH];
__device__ float d_gi [(size_t)M_TOTAL*G3];        // x @ Wih^T + bih + bhh
__device__ float d_hs [(size_t)M_TOTAL*HH];        // GRU hidden states

// ---------------- packed f32x2 helpers ----------------
#define FMA2(acc, a, b) asm("fma.rn.f32x2 %0, %1, %2, %0;" : "+l"(acc) : "l"(a), "l"(b))
__device__ __forceinline__ float f2sum(unsigned long long v) {
    float lo, hi;
    asm("mov.b64 {%0,%1}, %2;" : "=f"(lo), "=f"(hi) : "l"(v));
    return lo + hi;
}

// fast sigmoid / tanh via MUFU
__device__ __forceinline__ float sigf(float x) {
    float e, r;
    asm("ex2.approx.f32 %0, %1;" : "=f"(e) : "f"(-1.4426950408889634f * x));
    asm("rcp.approx.f32 %0, %1;" : "=f"(r) : "f"(1.0f + e));
    return r;
}
__device__ __forceinline__ float tanhfast(float x) {
    return fmaf(2.0f, sigf(2.0f * x), -1.0f);
}

// ---------------- warp MMA helpers (sm_80+ baseline features) ----------------
__device__ __forceinline__ uint32_t smem_u32(const void* p) {
    uint32_t a;
    asm("{ .reg .u64 t; cvta.to.shared.u64 t, %1; cvt.u32.u64 %0, t; }"
        : "=r"(a) : "l"(p));
    return a;
}
__device__ __forceinline__ void ldsm4(uint32_t* r, uint32_t addr) {
    asm volatile("ldmatrix.sync.aligned.m8n8.x4.shared.b16 {%0,%1,%2,%3}, [%4];"
        : "=r"(r[0]), "=r"(r[1]), "=r"(r[2]), "=r"(r[3]) : "r"(addr));
}
__device__ __forceinline__ void mma16816(float* d, const uint32_t* a, const uint32_t* b) {
    asm volatile("mma.sync.aligned.m16n8k16.row.col.f32.bf16.bf16.f32 "
        "{%0,%1,%2,%3}, {%4,%5,%6,%7}, {%8,%9}, {%0,%1,%2,%3};"
        : "+f"(d[0]), "+f"(d[1]), "+f"(d[2]), "+f"(d[3])
        : "r"(a[0]), "r"(a[1]), "r"(a[2]), "r"(a[3]), "r"(b[0]), "r"(b[1]));
}

// ---------------- generic 32x32 tiled transpose ----------------
__global__ void transpose_kernel(const float* __restrict__ src, float* __restrict__ dst,
                                 int R, int C) {
    __shared__ float tile[32][33];
    int c0 = blockIdx.x * 32, r0 = blockIdx.y * 32;
    int tx = threadIdx.x, ty = threadIdx.y;
    #pragma unroll
    for (int j = 0; j < 32; j += 8) {
        int r = r0 + ty + j, c = c0 + tx;
        if (r < R && c < C) tile[ty + j][tx] = src[(size_t)r * C + c];
    }
    __syncthreads();
    #pragma unroll
    for (int j = 0; j < 32; j += 8) {
        int r = r0 + tx, c = c0 + ty + j;
        if (c < C && r < R) dst[(size_t)c * R + r] = tile[tx][ty + j];
    }
}

// ---------------- block-wide sum over 128 threads ----------------
__device__ __forceinline__ float blocksum128(float v, float* sb) {
    #pragma unroll
    for (int o = 16; o; o >>= 1) v += __shfl_xor_sync(0xffffffffu, v, o);
    if ((threadIdx.x & 31) == 0) sb[threadIdx.x >> 5] = v;
    __syncthreads();
    float r = sb[0] + sb[1] + sb[2] + sb[3];
    __syncthreads();
    return r;
}

// ---------------- K0b: Wih split into bf16 hi/lo ----------------
__global__ void wsplit(const float* __restrict__ w,
                       __nv_bfloat16* __restrict__ whi, __nv_bfloat16* __restrict__ wlo) {
    int i = blockIdx.x * 256 + threadIdx.x;
    if (i < G3 * HH) {
        float v = w[i];
        __nv_bfloat16 h = __float2bfloat16(v);
        whi[i] = h;
        wlo[i] = __float2bfloat16(v - __bfloat162float(h));
    }
}

// ---------------- K1: embedding gather + LayerNorm1 -> bf16 hi/lo ----------------
__global__ void embed_ln1(const int* __restrict__ seqs,
                          const float* __restrict__ g1, const float* __restrict__ b1,
                          __nv_bfloat16* __restrict__ xhi, __nv_bfloat16* __restrict__ xlo) {
    __shared__ float sb[4];
    int idx = blockIdx.x;            // b*TT + t
    int b = idx / TT, t = idx - b * TT;
    int tid = threadIdx.x;           // 128
    int tok = seqs[b * (TT + 1) + t];
    float e  = d_embT[(size_t)tok * HH + tid];
    float mu = blocksum128(e, sb) * (1.0f / HH);
    float d  = e - mu;
    float var = blocksum128(d * d, sb) * (1.0f / HH);
    float xn = d * rsqrtf(var + 1e-8f) * g1[tid] + b1[tid];
    __nv_bfloat16 h = __float2bfloat16(xn);
    xhi[(size_t)idx * HH + tid] = h;
    xlo[(size_t)idx * HH + tid] = __float2bfloat16(xn - __bfloat162float(h));
}

// ---------------- K2: warp-MMA GEMM  gi = x @ Wih^T + (bih+bhh) ----------------
// CTA 512 threads (16 warps), tile M=256 x N=128, K=128.
// Split bf16: D = Ah*Bh + Ah*Bl + Al*Bh (fp32 accumulate in registers).
// smem pitch 136 bf16 (272 B) -> ldmatrix bank-conflict-free.
#define PA   136
#define PAB  272
#define OFF_AH   0
#define OFF_AL   (256 * PAB)              // 69632
#define OFF_BH   (2 * 256 * PAB)          // 139264
#define OFF_BL   (OFF_BH + 128 * PAB)     // 174080
#define OFF_BIAS (OFF_BH + 2 * 128 * PAB) // 208896
#define GEMM_SMEM (OFF_BIAS + 1024)       // 209920

__global__ __launch_bounds__(512, 1)
void gemm_tc(const __nv_bfloat16* __restrict__ xhi, const __nv_bfloat16* __restrict__ xlo,
             const __nv_bfloat16* __restrict__ whi, const __nv_bfloat16* __restrict__ wlo,
             const float* __restrict__ bih, const float* __restrict__ bhh,
             float* __restrict__ gi) {
    extern __shared__ char sm[];
    uint32_t smb = smem_u32(sm);
    float* biassh = (float*)(sm + OFF_BIAS);
    int tid = threadIdx.x;
    int m0 = blockIdx.x * 256;
    int n0 = blockIdx.y * 128;

    // stage A (hi+lo): 256 rows x 16 chunks of 8 bf16
    #pragma unroll
    for (int i = tid; i < 256 * 16; i += 512) {
        int row = i >> 4, ch = i & 15;
        size_t ga = ((size_t)(m0 + row)) * HH + ch * 8;
        uint32_t so = (uint32_t)row * PAB + ch * 16;
        *(uint4*)(sm + OFF_AH + so) = *(const uint4*)&xhi[ga];
        *(uint4*)(sm + OFF_AL + so) = *(const uint4*)&xlo[ga];
    }
    // stage B (hi+lo): 128 rows (n) x 16 chunks
    #pragma unroll
    for (int i = tid; i < 128 * 16; i += 512) {
        int row = i >> 4, ch = i & 15;
        size_t ga = ((size_t)(n0 + row)) * HH + ch * 8;
        uint32_t so = (uint32_t)row * PAB + ch * 16;
        *(uint4*)(sm + OFF_BH + so) = *(const uint4*)&whi[ga];
        *(uint4*)(sm + OFF_BL + so) = *(const uint4*)&wlo[ga];
    }
    for (int i = tid; i < 128; i += 512) biassh[i] = bih[n0 + i] + bhh[n0 + i];
    __syncthreads();

    int wid = tid >> 5, l = tid & 31;
    int m_off = (wid >> 2) * 64;     // warp m offset in tile
    int nw    = (wid & 3) * 32;      // warp n offset in tile

    // ldmatrix lane address components (byte offsets within a buffer)
    uint32_t a_lane = smb + (uint32_t)(m_off + (l & 15)) * PAB + (uint32_t)(l >> 4) * 16;
    uint32_t b_lane = smb + (uint32_t)(nw + (l & 7) + ((l >= 16) ? 8 : 0)) * PAB
                          + (uint32_t)((l & 8) ? 16 : 0);

    float acc[4][4][4];
    #pragma unroll
    for (int mt = 0; mt < 4; mt++)
        #pragma unroll
        for (int nt = 0; nt < 4; nt++)
            #pragma unroll
            for (int r = 0; r < 4; r++) acc[mt][nt][r] = 0.f;

    #pragma unroll 1
    for (int ks = 0; ks < 8; ks++) {
        #pragma unroll 1
        for (int pass = 0; pass < 3; pass++) {
            uint32_t aoff = ((pass < 2) ? OFF_AH : OFF_AL) + ks * 32;
            uint32_t boff = ((pass == 1) ? OFF_BL : OFF_BH) + ks * 32;
            uint32_t af[4][4];
            #pragma unroll
            for (int mt = 0; mt < 4; mt++)
                ldsm4(af[mt], a_lane + aoff + mt * 16 * PAB);
            uint32_t bf[2][4];
            #pragma unroll
            for (int np = 0; np < 2; np++)
                ldsm4(bf[np], b_lane + boff + np * 16 * PAB);
            #pragma unroll
            for (int mt = 0; mt < 4; mt++)
                #pragma unroll
                for (int nt = 0; nt < 4; nt++)
                    mma16816(acc[mt][nt], af[mt], &bf[nt >> 1][(nt & 1) * 2]);
        }
    }

    // epilogue: add bias, store float2 pairs
    #pragma unroll
    for (int mt = 0; mt < 4; mt++) {
        #pragma unroll
        for (int nt = 0; nt < 4; nt++) {
            int m1 = m0 + m_off + mt * 16 + (l >> 2);
            int nn = nw + nt * 8 + 2 * (l & 3);
            float b0 = biassh[nn], b1 = biassh[nn + 1];
            float2 s0 = make_float2(acc[mt][nt][0] + b0, acc[mt][nt][1] + b1);
            float2 s1 = make_float2(acc[mt][nt][2] + b0, acc[mt][nt][3] + b1);
            *(float2*)&gi[(size_t)m1 * G3 + n0 + nn]       = s0;
            *(float2*)&gi[(size_t)(m1 + 8) * G3 + n0 + nn] = s1;
        }
    }
}

// ---------------- K3: GRU recurrence (unchanged from R7) ----------------
#define HP   144
#define GHPS 1544
__global__ __launch_bounds__(512)
void gru_rec(const float* __restrict__ gi, const float* __restrict__ Whh,
             float* __restrict__ hs) {
    __shared__ float hsh[4 * HP];
    __shared__ float ghp[4 * GHPS];
    int tid = threadIdx.x;
    int kp = tid & 3, rp = tid >> 2;
    int s0 = blockIdx.x * 4;

    unsigned long long w[48];
    {
        const float* wb = Whh + (size_t)rp * 128 + kp * 32;
        #pragma unroll
        for (int r = 0; r < 3; r++) {
            const ulonglong2* p = (const ulonglong2*)(wb + (size_t)r * 128 * 128);
            #pragma unroll
            for (int i = 0; i < 8; i++) {
                ulonglong2 v = p[i];
                w[r * 16 + 2 * i]     = v.x;
                w[r * 16 + 2 * i + 1] = v.y;
            }
        }
    }

    int su = tid >> 7, ju = tid & 127;
    const float* gp = gi + ((size_t)(s0 + su) * TT) * G3 + ju;
    float* hp = hs + ((size_t)(s0 + su) * TT) * HH + ju;
    float hreg = 0.f;

    for (int i = tid; i < 4 * HP; i += 512) hsh[i] = 0.f;
    __syncthreads();

    float* gout = &ghp[kp * GHPS + rp];

    for (int t = 0; t < TT; t++) {
        float ir  = gp[0];
        float iz  = gp[128];
        float inn = gp[256];

        #pragma unroll 1
        for (int seq = 0; seq < 4; seq++) {
            unsigned long long a0 = 0ull, a1 = 0ull, a2 = 0ull;
            const ulonglong2* hq = (const ulonglong2*)&hsh[seq * HP + kp * 36];
            #pragma unroll
            for (int i = 0; i < 8; i++) {
                ulonglong2 hv = hq[i];
                FMA2(a0, w[2 * i],      hv.x); FMA2(a0, w[2 * i + 1],      hv.y);
                FMA2(a1, w[16 + 2 * i], hv.x); FMA2(a1, w[16 + 2 * i + 1], hv.y);
                FMA2(a2, w[32 + 2 * i], hv.x); FMA2(a2, w[32 + 2 * i + 1], hv.y);
            }
            float* go = gout + seq * 384;
            go[0]   = f2sum(a0);
            go[128] = f2sum(a1);
            go[256] = f2sum(a2);
        }
        __syncthreads();

        {
            int u = su * 384 + ju;
            const float* g0 = &ghp[u];
            const float* g1 = &ghp[GHPS + u];
            const float* g2 = &ghp[2 * GHPS + u];
            const float* g3 = &ghp[3 * GHPS + u];
            float hr = (g0[0]   + g1[0])   + (g2[0]   + g3[0]);
            float hz = (g0[128] + g1[128]) + (g2[128] + g3[128]);
            float hn = (g0[256] + g1[256]) + (g2[256] + g3[256]);
            float r = sigf(ir + hr);
            float z = sigf(iz + hz);
            float n = tanhfast(inn + r * hn);
            float hnew = (1.f - z) * n + z * hreg;
            hreg = hnew;
            hsh[su * HP + (ju >> 5) * 36 + (ju & 31)] = hnew;
            *hp = hnew;
            gp += G3;
            hp += HH;
        }
        __syncthreads();
    }
}

// ---------------- K4: LayerNorm2 + pos/neg dot products ----------------
__global__ void final_logits(const int* __restrict__ seqs, const int* __restrict__ negs,
                             const float* __restrict__ g2, const float* __restrict__ b2,
                             float* __restrict__ out) {
    __shared__ float sb[4];
    int idx = blockIdx.x;
    int b = idx / TT, t = idx - b * TT;
    int tid = threadIdx.x;          // 128
    float v  = d_hs[(size_t)idx * HH + tid];
    float mu = blocksum128(v, sb) * (1.0f / HH);
    float d  = v - mu;
    float var = blocksum128(d * d, sb) * (1.0f / HH);
    float ln = d * rsqrtf(var + 1e-8f) * g2[tid] + b2[tid];

    int pt = seqs[b * (TT + 1) + t + 1];
    int nt = negs[b * (TT + 1) + t + 1];
    float pv = ln * d_embT[(size_t)pt * HH + tid];
    float nv = ln * d_embT[(size_t)nt * HH + tid];
    float ps = blocksum128(pv, sb);
    float ns = blocksum128(nv, sb);
    if (tid == 0) {
        out[idx]           = ps;
        out[M_TOTAL + idx] = ns;
    }
}

// ---------------- launch ----------------
extern "C" void kernel_launch(void* const* d_in, const int* in_sizes, int n_in,
                              void* d_out, int out_size) {
    const int*   input_seqs = (const int*)  d_in[0];
    const int*   negs       = (const int*)  d_in[1];
    const float* emb_W      = (const float*)d_in[2];
    const float* Wih        = (const float*)d_in[3];
    const float* Whh        = (const float*)d_in[4];
    const float* bih        = (const float*)d_in[5];
    const float* bhh        = (const float*)d_in[6];
    const float* ln1_g      = (const float*)d_in[7];
    const float* ln1_b      = (const float*)d_in[8];
    const float* ln2_g      = (const float*)d_in[9];
    const float* ln2_b      = (const float*)d_in[10];
    float* out = (float*)d_out;

    float* p_embT; cudaGetSymbolAddress((void**)&p_embT, d_embT);
    __nv_bfloat16* p_xhi; cudaGetSymbolAddress((void**)&p_xhi, d_xhi);
    __nv_bfloat16* p_xlo; cudaGetSymbolAddress((void**)&p_xlo, d_xlo);
    __nv_bfloat16* p_whi; cudaGetSymbolAddress((void**)&p_whi, d_whi);
    __nv_bfloat16* p_wlo; cudaGetSymbolAddress((void**)&p_wlo, d_wlo);
    float* p_gi;   cudaGetSymbolAddress((void**)&p_gi,   d_gi);
    float* p_hs;   cudaGetSymbolAddress((void**)&p_hs,   d_hs);

    transpose_kernel<<<dim3((VV + 31) / 32, 4), dim3(32, 8)>>>(emb_W, p_embT, HH, VV);
    wsplit<<<(G3 * HH + 255) / 256, 256>>>(Wih, p_whi, p_wlo);

    embed_ln1<<<M_TOTAL, 128>>>(input_seqs, ln1_g, ln1_b, p_xhi, p_xlo);

    cudaFuncSetAttribute(gemm_tc, cudaFuncAttributeMaxDynamicSharedMemorySize, GEMM_SMEM);
    gemm_tc<<<dim3(M_TOTAL / 256, G3 / 128), 512, GEMM_SMEM>>>(
        p_xhi, p_xlo, p_whi, p_wlo, bih, bhh, p_gi);

    gru_rec<<<BB / 4, 512>>>(p_gi, Whh, p_hs);

    final_logits<<<M_TOTAL, 128>>>(input_seqs, negs, ln2_g, ln2_b, out);
}

// round 13
// speedup vs baseline: 2.0810x; 1.0161x over previous
#include <cuda_runtime.h>
#include <cuda_bf16.h>
#include <math.h>
#include <cstdint>

#define BB 512
#define TT 200
#define HH 128
#define VV 100001
#define G3 384
#define M_TOTAL (BB*TT)   // 102400

// ---------------- scratch ----------------
__device__ float d_embT[(size_t)VV*HH];            // (V, H) = emb_W^T
__device__ __nv_bfloat16 d_xhi[(size_t)M_TOTAL*HH];
__device__ __nv_bfloat16 d_xlo[(size_t)M_TOTAL*HH];
__device__ __nv_bfloat16 d_whi[G3*HH];
__device__ __nv_bfloat16 d_wlo[G3*HH];
__device__ float d_gi [(size_t)M_TOTAL*G3];        // x @ Wih^T + bih + bhh
__device__ float d_hs [(size_t)M_TOTAL*HH];        // GRU hidden states

// ---------------- packed f32x2 helpers ----------------
#define FMA2(acc, a, b) asm("fma.rn.f32x2 %0, %1, %2, %0;" : "+l"(acc) : "l"(a), "l"(b))
__device__ __forceinline__ float f2sum(unsigned long long v) {
    float lo, hi;
    asm("mov.b64 {%0,%1}, %2;" : "=f"(lo), "=f"(hi) : "l"(v));
    return lo + hi;
}

// fast sigmoid / tanh via MUFU
__device__ __forceinline__ float sigf(float x) {
    float e, r;
    asm("ex2.approx.f32 %0, %1;" : "=f"(e) : "f"(-1.4426950408889634f * x));
    asm("rcp.approx.f32 %0, %1;" : "=f"(r) : "f"(1.0f + e));
    return r;
}
__device__ __forceinline__ float tanhfast(float x) {
    return fmaf(2.0f, sigf(2.0f * x), -1.0f);
}

// ---------------- warp MMA helpers ----------------
__device__ __forceinline__ uint32_t smem_u32(const void* p) {
    uint32_t a;
    asm("{ .reg .u64 t; cvta.to.shared.u64 t, %1; cvt.u32.u64 %0, t; }"
        : "=r"(a) : "l"(p));
    return a;
}
__device__ __forceinline__ void ldsm4(uint32_t* r, uint32_t addr) {
    asm volatile("ldmatrix.sync.aligned.m8n8.x4.shared.b16 {%0,%1,%2,%3}, [%4];"
        : "=r"(r[0]), "=r"(r[1]), "=r"(r[2]), "=r"(r[3]) : "r"(addr));
}
__device__ __forceinline__ void mma16816(float* d, const uint32_t* a, const uint32_t* b) {
    asm volatile("mma.sync.aligned.m16n8k16.row.col.f32.bf16.bf16.f32 "
        "{%0,%1,%2,%3}, {%4,%5,%6,%7}, {%8,%9}, {%0,%1,%2,%3};"
        : "+f"(d[0]), "+f"(d[1]), "+f"(d[2]), "+f"(d[3])
        : "r"(a[0]), "r"(a[1]), "r"(a[2]), "r"(a[3]), "r"(b[0]), "r"(b[1]));
}

// ---------------- generic 32x32 tiled transpose ----------------
__global__ void transpose_kernel(const float* __restrict__ src, float* __restrict__ dst,
                                 int R, int C) {
    __shared__ float tile[32][33];
    int c0 = blockIdx.x * 32, r0 = blockIdx.y * 32;
    int tx = threadIdx.x, ty = threadIdx.y;
    #pragma unroll
    for (int j = 0; j < 32; j += 8) {
        int r = r0 + ty + j, c = c0 + tx;
        if (r < R && c < C) tile[ty + j][tx] = src[(size_t)r * C + c];
    }
    __syncthreads();
    #pragma unroll
    for (int j = 0; j < 32; j += 8) {
        int r = r0 + tx, c = c0 + ty + j;
        if (c < C && r < R) dst[(size_t)c * R + r] = tile[tx][ty + j];
    }
}

// ---------------- block-wide sum over 128 threads ----------------
__device__ __forceinline__ float blocksum128(float v, float* sb) {
    #pragma unroll
    for (int o = 16; o; o >>= 1) v += __shfl_xor_sync(0xffffffffu, v, o);
    if ((threadIdx.x & 31) == 0) sb[threadIdx.x >> 5] = v;
    __syncthreads();
    float r = sb[0] + sb[1] + sb[2] + sb[3];
    __syncthreads();
    return r;
}

// ---------------- K0b: Wih split into bf16 hi/lo ----------------
__global__ void wsplit(const float* __restrict__ w,
                       __nv_bfloat16* __restrict__ whi, __nv_bfloat16* __restrict__ wlo) {
    int i = blockIdx.x * 256 + threadIdx.x;
    if (i < G3 * HH) {
        float v = w[i];
        __nv_bfloat16 h = __float2bfloat16(v);
        whi[i] = h;
        wlo[i] = __float2bfloat16(v - __bfloat162float(h));
    }
}

// ---------------- K1: embedding gather + LayerNorm1 -> bf16 hi/lo ----------------
__global__ void embed_ln1(const int* __restrict__ seqs,
                          const float* __restrict__ g1, const float* __restrict__ b1,
                          __nv_bfloat16* __restrict__ xhi, __nv_bfloat16* __restrict__ xlo) {
    __shared__ float sb[4];
    int idx = blockIdx.x;            // b*TT + t
    int b = idx / TT, t = idx - b * TT;
    int tid = threadIdx.x;           // 128
    int tok = seqs[b * (TT + 1) + t];
    float e  = d_embT[(size_t)tok * HH + tid];
    float mu = blocksum128(e, sb) * (1.0f / HH);
    float d  = e - mu;
    float var = blocksum128(d * d, sb) * (1.0f / HH);
    float xn = d * rsqrtf(var + 1e-8f) * g1[tid] + b1[tid];
    __nv_bfloat16 h = __float2bfloat16(xn);
    xhi[(size_t)idx * HH + tid] = h;
    xlo[(size_t)idx * HH + tid] = __float2bfloat16(xn - __bfloat162float(h));
}

// ---------------- K2: warp-MMA GEMM  gi = x @ Wih^T + (bih+bhh) ----------------
// CTA 512 threads = 16 warps in 4x4, tile M=128 x N=128, warp 32x32, K=128.
// Split bf16: D = Ah*Bh + Ah*Bl + Al*Bh (fp32 regs).
// Pitch 272 B: 16B-aligned rows (ldmatrix/uint4 legal); 16B-chunk stride 17
// (odd) -> each ldmatrix 8-row phase hits 8 distinct chunks, conflict-free.
// Per kstep: 8 ldmatrix.x4 (afH,afL,bfH,bfL) feed 24 MMA (3:1).
#define PAB  272
#define OFF_AH   0
#define OFF_AL   (128 * PAB)              // 34816
#define OFF_BH   (2 * 128 * PAB)          // 69632
#define OFF_BL   (3 * 128 * PAB)          // 104448
#define OFF_BIAS (4 * 128 * PAB)          // 139264
#define GEMM_SMEM (OFF_BIAS + 512)        // 139776

__global__ __launch_bounds__(512, 1)
void gemm_tc(const __nv_bfloat16* __restrict__ xhi, const __nv_bfloat16* __restrict__ xlo,
             const __nv_bfloat16* __restrict__ whi, const __nv_bfloat16* __restrict__ wlo,
             const float* __restrict__ bih, const float* __restrict__ bhh,
             float* __restrict__ gi) {
    extern __shared__ char sm[];
    uint32_t smb = smem_u32(sm);
    float* biassh = (float*)(sm + OFF_BIAS);
    int tid = threadIdx.x;
    int n0 = blockIdx.x * 128;      // fast dim = n -> A tiles L2-reused
    int m0 = blockIdx.y * 128;

    // stage A (hi+lo): 128 rows x 16 chunks of 16B
    #pragma unroll
    for (int i = tid; i < 128 * 16; i += 512) {
        int row = i >> 4, ch = i & 15;
        size_t ga = ((size_t)(m0 + row)) * HH + ch * 8;
        uint32_t so = (uint32_t)row * PAB + ch * 16;
        *(uint4*)(sm + OFF_AH + so) = *(const uint4*)&xhi[ga];
        *(uint4*)(sm + OFF_AL + so) = *(const uint4*)&xlo[ga];
    }
    // stage B (hi+lo): 128 n-rows x 16 chunks
    #pragma unroll
    for (int i = tid; i < 128 * 16; i += 512) {
        int row = i >> 4, ch = i & 15;
        size_t ga = ((size_t)(n0 + row)) * HH + ch * 8;
        uint32_t so = (uint32_t)row * PAB + ch * 16;
        *(uint4*)(sm + OFF_BH + so) = *(const uint4*)&whi[ga];
        *(uint4*)(sm + OFF_BL + so) = *(const uint4*)&wlo[ga];
    }
    for (int i = tid; i < 128; i += 512) biassh[i] = bih[n0 + i] + bhh[n0 + i];
    __syncthreads();

    int wid = tid >> 5, l = tid & 31;
    int m_off = (wid >> 2) * 32;     // warp m offset (0,32,64,96)
    int nw    = (wid & 3) * 32;      // warp n offset

    uint32_t a_lane = smb + (uint32_t)(m_off + (l & 15)) * PAB + (uint32_t)(l >> 4) * 16;
    uint32_t b_lane = smb + (uint32_t)(nw + (l & 7) + ((l >= 16) ? 8 : 0)) * PAB
                          + (uint32_t)((l & 8) ? 16 : 0);

    float acc[2][4][4];
    #pragma unroll
    for (int mt = 0; mt < 2; mt++)
        #pragma unroll
        for (int nt = 0; nt < 4; nt++)
            #pragma unroll
            for (int r = 0; r < 4; r++) acc[mt][nt][r] = 0.f;

    #pragma unroll 1
    for (int ks = 0; ks < 8; ks++) {
        uint32_t ko = ks * 32;
        uint32_t afH[2][4], afL[2][4], bfH[2][4], bfL[2][4];
        #pragma unroll
        for (int mt = 0; mt < 2; mt++) {
            ldsm4(afH[mt], a_lane + OFF_AH + ko + mt * 16 * PAB);
            ldsm4(afL[mt], a_lane + OFF_AL + ko + mt * 16 * PAB);
        }
        #pragma unroll
        for (int np = 0; np < 2; np++) {
            ldsm4(bfH[np], b_lane + OFF_BH + ko + np * 16 * PAB);
            ldsm4(bfL[np], b_lane + OFF_BL + ko + np * 16 * PAB);
        }
        #pragma unroll
        for (int mt = 0; mt < 2; mt++)
            #pragma unroll
            for (int nt = 0; nt < 4; nt++) {
                mma16816(acc[mt][nt], afH[mt], &bfH[nt >> 1][(nt & 1) * 2]);
                mma16816(acc[mt][nt], afH[mt], &bfL[nt >> 1][(nt & 1) * 2]);
                mma16816(acc[mt][nt], afL[mt], &bfH[nt >> 1][(nt & 1) * 2]);
            }
    }

    // epilogue: add bias, store float2 pairs
    #pragma unroll
    for (int mt = 0; mt < 2; mt++) {
        #pragma unroll
        for (int nt = 0; nt < 4; nt++) {
            int m1 = m0 + m_off + mt * 16 + (l >> 2);
            int nn = nw + nt * 8 + 2 * (l & 3);
            float b0 = biassh[nn], b1 = biassh[nn + 1];
            float2 s0 = make_float2(acc[mt][nt][0] + b0, acc[mt][nt][1] + b1);
            float2 s1 = make_float2(acc[mt][nt][2] + b0, acc[mt][nt][3] + b1);
            *(float2*)&gi[(size_t)m1 * G3 + n0 + nn]       = s0;
            *(float2*)&gi[(size_t)(m1 + 8) * G3 + n0 + nn] = s1;
        }
    }
}

// ---------------- K3: GRU recurrence (unchanged) ----------------
#define HP   144
#define GHPS 1544
__global__ __launch_bounds__(512)
void gru_rec(const float* __restrict__ gi, const float* __restrict__ Whh,
             float* __restrict__ hs) {
    __shared__ float hsh[4 * HP];
    __shared__ float ghp[4 * GHPS];
    int tid = threadIdx.x;
    int kp = tid & 3, rp = tid >> 2;
    int s0 = blockIdx.x * 4;

    unsigned long long w[48];
    {
        const float* wb = Whh + (size_t)rp * 128 + kp * 32;
        #pragma unroll
        for (int r = 0; r < 3; r++) {
            const ulonglong2* p = (const ulonglong2*)(wb + (size_t)r * 128 * 128);
            #pragma unroll
            for (int i = 0; i < 8; i++) {
                ulonglong2 v = p[i];
                w[r * 16 + 2 * i]     = v.x;
                w[r * 16 + 2 * i + 1] = v.y;
            }
        }
    }

    int su = tid >> 7, ju = tid & 127;
    const float* gp = gi + ((size_t)(s0 + su) * TT) * G3 + ju;
    float* hp = hs + ((size_t)(s0 + su) * TT) * HH + ju;
    float hreg = 0.f;

    for (int i = tid; i < 4 * HP; i += 512) hsh[i] = 0.f;
    __syncthreads();

    float* gout = &ghp[kp * GHPS + rp];

    for (int t = 0; t < TT; t++) {
        float ir  = gp[0];
        float iz  = gp[128];
        float inn = gp[256];

        #pragma unroll 1
        for (int seq = 0; seq < 4; seq++) {
            unsigned long long a0 = 0ull, a1 = 0ull, a2 = 0ull;
            const ulonglong2* hq = (const ulonglong2*)&hsh[seq * HP + kp * 36];
            #pragma unroll
            for (int i = 0; i < 8; i++) {
                ulonglong2 hv = hq[i];
                FMA2(a0, w[2 * i],      hv.x); FMA2(a0, w[2 * i + 1],      hv.y);
                FMA2(a1, w[16 + 2 * i], hv.x); FMA2(a1, w[16 + 2 * i + 1], hv.y);
                FMA2(a2, w[32 + 2 * i], hv.x); FMA2(a2, w[32 + 2 * i + 1], hv.y);
            }
            float* go = gout + seq * 384;
            go[0]   = f2sum(a0);
            go[128] = f2sum(a1);
            go[256] = f2sum(a2);
        }
        __syncthreads();

        {
            int u = su * 384 + ju;
            const float* g0 = &ghp[u];
            const float* g1 = &ghp[GHPS + u];
            const float* g2 = &ghp[2 * GHPS + u];
            const float* g3 = &ghp[3 * GHPS + u];
            float hr = (g0[0]   + g1[0])   + (g2[0]   + g3[0]);
            float hz = (g0[128] + g1[128]) + (g2[128] + g3[128]);
            float hn = (g0[256] + g1[256]) + (g2[256] + g3[256]);
            float r = sigf(ir + hr);
            float z = sigf(iz + hz);
            float n = tanhfast(inn + r * hn);
            float hnew = (1.f - z) * n + z * hreg;
            hreg = hnew;
            hsh[su * HP + (ju >> 5) * 36 + (ju & 31)] = hnew;
            *hp = hnew;
            gp += G3;
            hp += HH;
        }
        __syncthreads();
    }
}

// ---------------- K4: LayerNorm2 + pos/neg dot products ----------------
__global__ void final_logits(const int* __restrict__ seqs, const int* __restrict__ negs,
                             const float* __restrict__ g2, const float* __restrict__ b2,
                             float* __restrict__ out) {
    __shared__ float sb[4];
    int idx = blockIdx.x;
    int b = idx / TT, t = idx - b * TT;
    int tid = threadIdx.x;          // 128
    float v  = d_hs[(size_t)idx * HH + tid];
    float mu = blocksum128(v, sb) * (1.0f / HH);
    float d  = v - mu;
    float var = blocksum128(d * d, sb) * (1.0f / HH);
    float ln = d * rsqrtf(var + 1e-8f) * g2[tid] + b2[tid];

    int pt = seqs[b * (TT + 1) + t + 1];
    int nt = negs[b * (TT + 1) + t + 1];
    float pv = ln * d_embT[(size_t)pt * HH + tid];
    float nv = ln * d_embT[(size_t)nt * HH + tid];
    float ps = blocksum128(pv, sb);
    float ns = blocksum128(nv, sb);
    if (tid == 0) {
        out[idx]           = ps;
        out[M_TOTAL + idx] = ns;
    }
}

// ---------------- launch ----------------
extern "C" void kernel_launch(void* const* d_in, const int* in_sizes, int n_in,
                              void* d_out, int out_size) {
    const int*   input_seqs = (const int*)  d_in[0];
    const int*   negs       = (const int*)  d_in[1];
    const float* emb_W      = (const float*)d_in[2];
    const float* Wih        = (const float*)d_in[3];
    const float* Whh        = (const float*)d_in[4];
    const float* bih        = (const float*)d_in[5];
    const float* bhh        = (const float*)d_in[6];
    const float* ln1_g      = (const float*)d_in[7];
    const float* ln1_b      = (const float*)d_in[8];
    const float* ln2_g      = (const float*)d_in[9];
    const float* ln2_b      = (const float*)d_in[10];
    float* out = (float*)d_out;

    float* p_embT; cudaGetSymbolAddress((void**)&p_embT, d_embT);
    __nv_bfloat16* p_xhi; cudaGetSymbolAddress((void**)&p_xhi, d_xhi);
    __nv_bfloat16* p_xlo; cudaGetSymbolAddress((void**)&p_xlo, d_xlo);
    __nv_bfloat16* p_whi; cudaGetSymbolAddress((void**)&p_whi, d_whi);
    __nv_bfloat16* p_wlo; cudaGetSymbolAddress((void**)&p_wlo, d_wlo);
    float* p_gi;   cudaGetSymbolAddress((void**)&p_gi,   d_gi);
    float* p_hs;   cudaGetSymbolAddress((void**)&p_hs,   d_hs);

    transpose_kernel<<<dim3((VV + 31) / 32, 4), dim3(32, 8)>>>(emb_W, p_embT, HH, VV);
    wsplit<<<(G3 * HH + 255) / 256, 256>>>(Wih, p_whi, p_wlo);

    embed_ln1<<<M_TOTAL, 128>>>(input_seqs, ln1_g, ln1_b, p_xhi, p_xlo);

    cudaFuncSetAttribute(gemm_tc, cudaFuncAttributeMaxDynamicSharedMemorySize, GEMM_SMEM);
    gemm_tc<<<dim3(G3 / 128, M_TOTAL / 128), 512, GEMM_SMEM>>>(
        p_xhi, p_xlo, p_whi, p_wlo, bih, bhh, p_gi);

    gru_rec<<<BB / 4, 512>>>(p_gi, Whh, p_hs);

    final_logits<<<M_TOTAL, 128>>>(input_seqs, negs, ln2_g, ln2_b, out);
}